// round 1
// baseline (speedup 1.0000x reference)
#include <cuda_runtime.h>

#define NDIM 2304   // 48*48 tokens
#define CDIM 256
#define HEADS 8
#define HD 32

// scratch (no allocs allowed)
__device__ float g_q[CDIM * NDIM];
__device__ float g_k[CDIM * NDIM];
__device__ float g_v[CDIM * NDIM];
__device__ float g_o[CDIM * NDIM];

union U64 { unsigned long long u; float2 f; };

__device__ __forceinline__ void ffma2(unsigned long long& acc,
                                      unsigned long long a,
                                      unsigned long long b) {
    asm("fma.rn.f32x2 %0, %1, %2, %0;" : "+l"(acc) : "l"(a), "l"(b));
}

// ---------------------------------------------------------------------------
// GEMM: Y[o][n] = sum_c W[o][c] * X[c][n] + b[o];  M=256, K=256, N=2304
// 64x64 tile per CTA, 256 threads, 4x4 per thread, f32x2 packed FMA.
// ---------------------------------------------------------------------------
__device__ __forceinline__ void gemm_tile(const float* __restrict__ W,
                                          const float* __restrict__ bias,
                                          const float* __restrict__ X,
                                          float* __restrict__ Y) {
    __shared__ float2 wsd[16 * 64];  // [k][o], value duplicated {w,w}
    __shared__ float  xs [16 * 64];  // [k][n]

    const int tid = threadIdx.x;
    const int n0 = blockIdx.x * 64;
    const int o0 = blockIdx.y * 64;
    const int i0 = (tid >> 4) * 4;   // output row group
    const int j0 = (tid & 15) * 4;   // output col group

    U64 acc[4][2];
#pragma unroll
    for (int a = 0; a < 4; a++) { acc[a][0].u = 0ull; acc[a][1].u = 0ull; }

    const int ow = tid >> 2;
    const int kc = (tid & 3) * 4;
    const int xr = tid >> 6;
    const int xc = tid & 63;

    for (int k0 = 0; k0 < 256; k0 += 16) {
        __syncthreads();
        float4 w4 = *(const float4*)(W + (o0 + ow) * 256 + k0 + kc);
        wsd[(kc + 0) * 64 + ow] = make_float2(w4.x, w4.x);
        wsd[(kc + 1) * 64 + ow] = make_float2(w4.y, w4.y);
        wsd[(kc + 2) * 64 + ow] = make_float2(w4.z, w4.z);
        wsd[(kc + 3) * 64 + ow] = make_float2(w4.w, w4.w);
#pragma unroll
        for (int rr = 0; rr < 4; rr++)
            xs[(xr + rr * 4) * 64 + xc] = X[(k0 + xr + rr * 4) * NDIM + n0 + xc];
        __syncthreads();
#pragma unroll
        for (int k = 0; k < 16; k++) {
            ulonglong2 a01 = *(const ulonglong2*)(wsd + k * 64 + i0);
            ulonglong2 a23 = *(const ulonglong2*)(wsd + k * 64 + i0 + 2);
            ulonglong2 xp  = *(const ulonglong2*)(xs  + k * 64 + j0);
            ffma2(acc[0][0].u, a01.x, xp.x); ffma2(acc[0][1].u, a01.x, xp.y);
            ffma2(acc[1][0].u, a01.y, xp.x); ffma2(acc[1][1].u, a01.y, xp.y);
            ffma2(acc[2][0].u, a23.x, xp.x); ffma2(acc[2][1].u, a23.x, xp.y);
            ffma2(acc[3][0].u, a23.y, xp.x); ffma2(acc[3][1].u, a23.y, xp.y);
        }
    }
#pragma unroll
    for (int ii = 0; ii < 4; ii++) {
        float bv = bias[o0 + i0 + ii];
        float4 r = make_float4(acc[ii][0].f.x + bv, acc[ii][0].f.y + bv,
                               acc[ii][1].f.x + bv, acc[ii][1].f.y + bv);
        *(float4*)(Y + (o0 + i0 + ii) * NDIM + n0 + j0) = r;
    }
}

__global__ void __launch_bounds__(256)
qkv_kernel(const float* __restrict__ x,
           const float* __restrict__ Wq, const float* __restrict__ bq,
           const float* __restrict__ Wk, const float* __restrict__ bk,
           const float* __restrict__ Wv, const float* __restrict__ bv) {
    const float* W; const float* b; float* Y;
    if (blockIdx.z == 0)      { W = Wq; b = bq; Y = g_q; }
    else if (blockIdx.z == 1) { W = Wk; b = bk; Y = g_k; }
    else                      { W = Wv; b = bv; Y = g_v; }
    gemm_tile(W, b, x, Y);
}

__global__ void __launch_bounds__(256)
proj_kernel(const float* __restrict__ Wp, const float* __restrict__ bp,
            float* __restrict__ out) {
    gemm_tile(Wp, bp, g_o, out);
}

// ---------------------------------------------------------------------------
// Fused flash attention with analytic relative-position bias.
// CTA = (head h, 64 query rows). Online softmax over 36 key tiles of 64.
// ---------------------------------------------------------------------------
#define SM_QSD 0                          // float2[32*64]  = 16384 B
#define SM_KS  16384                      // float [32*64]  =  8192 B
#define SM_VST (16384 + 8192)             // float [64*34]  =  8704 B
#define SM_PSD (16384 + 8192 + 8704)      // float2[64*66]  = 33792 B
#define SM_EMB (SM_PSD + 33792)           // float [296]    =  1184 B
#define SM_TOTAL (SM_EMB + 1184)          // 68256 B

__global__ void __launch_bounds__(256, 2)
attn_kernel(const float* __restrict__ emb) {
    extern __shared__ char smraw[];
    float2* qsd  = (float2*)(smraw + SM_QSD);
    float*  ks   = (float*) (smraw + SM_KS);
    float*  vsT  = (float*) (smraw + SM_VST);
    float2* psd  = (float2*)(smraw + SM_PSD);
    float*  embs = (float*) (smraw + SM_EMB);

    const int h   = blockIdx.y;
    const int n0  = blockIdx.x * 64;
    const int tid = threadIdx.x;
    const int ti  = tid >> 4, tj = tid & 15;
    const int i0  = ti * 4,   j0 = tj * 4;
    const int d0  = tj * 2;

    // emb table into smem; pad row (36) forced to zero
    for (int idx = tid; idx < 296; idx += 256)
        embs[idx] = (idx >= 288) ? 0.f : emb[idx];

    const float* Qh = g_q + (h * HD) * NDIM;
    const float* Kh = g_k + (h * HD) * NDIM;
    const float* Vh = g_v + (h * HD) * NDIM;

    // Q tile (32 x 64) as duplicated f32x2 pairs, resident all kernel
#pragma unroll
    for (int e = 0; e < 8; e++) {
        int idx = tid + e * 256;
        int d = idx >> 6, i = idx & 63;
        float qv = Qh[d * NDIM + n0 + i];
        qsd[d * 64 + i] = make_float2(qv, qv);
    }

    int xn[4], yn[4];
#pragma unroll
    for (int ii = 0; ii < 4; ii++) {
        int n = n0 + i0 + ii;
        xn[ii] = n / 48; yn[ii] = n - 48 * xn[ii];
    }

    U64 o2[4];
#pragma unroll
    for (int ii = 0; ii < 4; ii++) o2[ii].u = 0ull;
    float mi[4] = {-1e30f, -1e30f, -1e30f, -1e30f};
    float li[4] = {0.f, 0.f, 0.f, 0.f};
    const float scale = 0.17677669529663687f;  // 32^-0.5

    for (int m0 = 0; m0 < NDIM; m0 += 64) {
        __syncthreads();
#pragma unroll
        for (int e = 0; e < 8; e++) {
            int idx = tid + e * 256;
            int d = idx >> 6, j = idx & 63;
            ks [d * 64 + j]  = Kh[d * NDIM + m0 + j];
            vsT[j * 34 + d]  = Vh[d * NDIM + m0 + j];
        }
        __syncthreads();

        // S = Q^T K  (4x4 per thread, packed over j pairs)
        U64 s2[4][2];
#pragma unroll
        for (int a = 0; a < 4; a++) { s2[a][0].u = 0ull; s2[a][1].u = 0ull; }
#pragma unroll
        for (int d = 0; d < 32; d++) {
            ulonglong2 qa = *(const ulonglong2*)(qsd + d * 64 + i0);
            ulonglong2 qb = *(const ulonglong2*)(qsd + d * 64 + i0 + 2);
            ulonglong2 kp = *(const ulonglong2*)(ks  + d * 64 + j0);
            ffma2(s2[0][0].u, qa.x, kp.x); ffma2(s2[0][1].u, qa.x, kp.y);
            ffma2(s2[1][0].u, qa.y, kp.x); ffma2(s2[1][1].u, qa.y, kp.y);
            ffma2(s2[2][0].u, qb.x, kp.x); ffma2(s2[2][1].u, qb.x, kp.y);
            ffma2(s2[3][0].u, qb.y, kp.x); ffma2(s2[3][1].u, qb.y, kp.y);
        }

        float s[4][4];
#pragma unroll
        for (int ii = 0; ii < 4; ii++) {
            s[ii][0] = s2[ii][0].f.x; s[ii][1] = s2[ii][0].f.y;
            s[ii][2] = s2[ii][1].f.x; s[ii][3] = s2[ii][1].f.y;
        }

        // scale + analytic relative-position bias
        int xm[4], ym[4];
#pragma unroll
        for (int jj = 0; jj < 4; jj++) {
            int m = m0 + j0 + jj;
            xm[jj] = m / 48; ym[jj] = m - 48 * xm[jj];
        }
#pragma unroll
        for (int ii = 0; ii < 4; ii++)
#pragma unroll
            for (int jj = 0; jj < 4; jj++) {
                int dx = xn[ii] - xm[jj]; dx = dx < 0 ? -dx : dx;
                int dy = yn[ii] - ym[jj]; dy = dy < 0 ? -dy : dy;
                float bb = (dx < 6 && dy < 6) ? embs[(dx * 6 + dy) * 8 + h] : 0.f;
                s[ii][jj] = s[ii][jj] * scale + bb;
            }

        // online softmax (row reductions across the 16 tj lanes)
        float mx[4];
#pragma unroll
        for (int ii = 0; ii < 4; ii++)
            mx[ii] = fmaxf(fmaxf(s[ii][0], s[ii][1]), fmaxf(s[ii][2], s[ii][3]));
#pragma unroll
        for (int off = 1; off < 16; off <<= 1)
#pragma unroll
            for (int ii = 0; ii < 4; ii++)
                mx[ii] = fmaxf(mx[ii], __shfl_xor_sync(0xffffffffu, mx[ii], off));

        float rf[4], rs[4];
#pragma unroll
        for (int ii = 0; ii < 4; ii++) {
            float mn = fmaxf(mi[ii], mx[ii]);
            rf[ii] = __expf(mi[ii] - mn);
            mi[ii] = mn;
            float p0 = __expf(s[ii][0] - mn);
            float p1 = __expf(s[ii][1] - mn);
            float p2 = __expf(s[ii][2] - mn);
            float p3 = __expf(s[ii][3] - mn);
            s[ii][0] = p0; s[ii][1] = p1; s[ii][2] = p2; s[ii][3] = p3;
            rs[ii] = (p0 + p1) + (p2 + p3);
        }
#pragma unroll
        for (int off = 1; off < 16; off <<= 1)
#pragma unroll
            for (int ii = 0; ii < 4; ii++)
                rs[ii] += __shfl_xor_sync(0xffffffffu, rs[ii], off);
#pragma unroll
        for (int ii = 0; ii < 4; ii++)
            li[ii] = li[ii] * rf[ii] + rs[ii];

        // stage P (duplicated pairs, transposed [j][i]) and rescale O
#pragma unroll
        for (int jj = 0; jj < 4; jj++)
#pragma unroll
            for (int ii = 0; ii < 4; ii++)
                psd[(j0 + jj) * 66 + i0 + ii] = make_float2(s[ii][jj], s[ii][jj]);
#pragma unroll
        for (int ii = 0; ii < 4; ii++) {
            o2[ii].f.x *= rf[ii];
            o2[ii].f.y *= rf[ii];
        }
        __syncthreads();

        // O[i][d0,d0+1] += sum_j P[i][j] * V[d][j]
#pragma unroll 8
        for (int j = 0; j < 64; j++) {
            ulonglong2 pa = *(const ulonglong2*)(psd + j * 66 + i0);
            ulonglong2 pb = *(const ulonglong2*)(psd + j * 66 + i0 + 2);
            unsigned long long vp = *(const unsigned long long*)(vsT + j * 34 + d0);
            ffma2(o2[0].u, pa.x, vp);
            ffma2(o2[1].u, pa.y, vp);
            ffma2(o2[2].u, pb.x, vp);
            ffma2(o2[3].u, pb.y, vp);
        }
    }

    float* Oh = g_o + (h * HD) * NDIM;
#pragma unroll
    for (int ii = 0; ii < 4; ii++) {
        float invl = 1.0f / li[ii];
        int n = n0 + i0 + ii;
        Oh[(d0 + 0) * NDIM + n] = o2[ii].f.x * invl;
        Oh[(d0 + 1) * NDIM + n] = o2[ii].f.y * invl;
    }
}

// ---------------------------------------------------------------------------
extern "C" void kernel_launch(void* const* d_in, const int* in_sizes, int n_in,
                              void* d_out, int out_size) {
    const float* x   = (const float*)d_in[0];
    const float* Wq  = (const float*)d_in[1];
    const float* bq  = (const float*)d_in[2];
    const float* Wk  = (const float*)d_in[3];
    const float* bk  = (const float*)d_in[4];
    const float* Wv  = (const float*)d_in[5];
    const float* bv  = (const float*)d_in[6];
    const float* Wp  = (const float*)d_in[7];
    const float* bp  = (const float*)d_in[8];
    const float* emb = (const float*)d_in[9];
    // d_in[10] = tokens (int32) — recomputed analytically in-kernel, unused
    float* out = (float*)d_out;

    cudaFuncSetAttribute(attn_kernel,
                         cudaFuncAttributeMaxDynamicSharedMemorySize, SM_TOTAL);

    qkv_kernel<<<dim3(36, 4, 3), 256>>>(x, Wq, bq, Wk, bk, Wv, bv);
    attn_kernel<<<dim3(36, HEADS), 256, SM_TOTAL>>>(emb);
    proj_kernel<<<dim3(36, 4), 256>>>(Wp, bp, out);
}

// round 2
// speedup vs baseline: 1.0031x; 1.0031x over previous
#include <cuda_runtime.h>

#define NDIM 2304   // 48*48 tokens
#define CDIM 256
#define HEADS 8
#define HD 32

// scratch (no allocs allowed)
__device__ float g_q[CDIM * NDIM];
__device__ float g_k[CDIM * NDIM];
__device__ float g_v[CDIM * NDIM];
__device__ float g_o[CDIM * NDIM];

union U64 { unsigned long long u; float2 f; };

__device__ __forceinline__ void ffma2(unsigned long long& acc,
                                      unsigned long long a,
                                      unsigned long long b) {
    asm("fma.rn.f32x2 %0, %1, %2, %0;" : "+l"(acc) : "l"(a), "l"(b));
}

// ---------------------------------------------------------------------------
// GEMM: Y[o][n] = sum_c W[o][c] * X[c][n] + b[o];  M=256, K=256, N=2304
// 64x64 tile per CTA, 256 threads, 4x4 per thread, f32x2 packed FMA.
// ---------------------------------------------------------------------------
__device__ __forceinline__ void gemm_tile(const float* __restrict__ W,
                                          const float* __restrict__ bias,
                                          const float* __restrict__ X,
                                          float* __restrict__ Y) {
    __shared__ float2 wsd[16 * 64];  // [k][o], value duplicated {w,w}
    __shared__ float  xs [16 * 64];  // [k][n]

    const int tid = threadIdx.x;
    const int n0 = blockIdx.x * 64;
    const int o0 = blockIdx.y * 64;
    const int i0 = (tid >> 4) * 4;   // output row group
    const int j0 = (tid & 15) * 4;   // output col group

    U64 acc[4][2];
#pragma unroll
    for (int a = 0; a < 4; a++) { acc[a][0].u = 0ull; acc[a][1].u = 0ull; }

    const int ow = tid >> 2;
    const int kc = (tid & 3) * 4;
    const int xr = tid >> 6;
    const int xc = tid & 63;

    for (int k0 = 0; k0 < 256; k0 += 16) {
        __syncthreads();
        float4 w4 = *(const float4*)(W + (o0 + ow) * 256 + k0 + kc);
        wsd[(kc + 0) * 64 + ow] = make_float2(w4.x, w4.x);
        wsd[(kc + 1) * 64 + ow] = make_float2(w4.y, w4.y);
        wsd[(kc + 2) * 64 + ow] = make_float2(w4.z, w4.z);
        wsd[(kc + 3) * 64 + ow] = make_float2(w4.w, w4.w);
#pragma unroll
        for (int rr = 0; rr < 4; rr++)
            xs[(xr + rr * 4) * 64 + xc] = X[(k0 + xr + rr * 4) * NDIM + n0 + xc];
        __syncthreads();
#pragma unroll
        for (int k = 0; k < 16; k++) {
            ulonglong2 a01 = *(const ulonglong2*)(wsd + k * 64 + i0);
            ulonglong2 a23 = *(const ulonglong2*)(wsd + k * 64 + i0 + 2);
            ulonglong2 xp  = *(const ulonglong2*)(xs  + k * 64 + j0);
            ffma2(acc[0][0].u, a01.x, xp.x); ffma2(acc[0][1].u, a01.x, xp.y);
            ffma2(acc[1][0].u, a01.y, xp.x); ffma2(acc[1][1].u, a01.y, xp.y);
            ffma2(acc[2][0].u, a23.x, xp.x); ffma2(acc[2][1].u, a23.x, xp.y);
            ffma2(acc[3][0].u, a23.y, xp.x); ffma2(acc[3][1].u, a23.y, xp.y);
        }
    }
#pragma unroll
    for (int ii = 0; ii < 4; ii++) {
        float bv = bias[o0 + i0 + ii];
        float4 r = make_float4(acc[ii][0].f.x + bv, acc[ii][0].f.y + bv,
                               acc[ii][1].f.x + bv, acc[ii][1].f.y + bv);
        *(float4*)(Y + (o0 + i0 + ii) * NDIM + n0 + j0) = r;
    }
}

__global__ void __launch_bounds__(256)
qkv_kernel(const float* __restrict__ x,
           const float* __restrict__ Wq, const float* __restrict__ bq,
           const float* __restrict__ Wk, const float* __restrict__ bk,
           const float* __restrict__ Wv, const float* __restrict__ bv) {
    const float* W; const float* b; float* Y;
    if (blockIdx.z == 0)      { W = Wq; b = bq; Y = g_q; }
    else if (blockIdx.z == 1) { W = Wk; b = bk; Y = g_k; }
    else                      { W = Wv; b = bv; Y = g_v; }
    gemm_tile(W, b, x, Y);
}

__global__ void __launch_bounds__(256)
proj_kernel(const float* __restrict__ Wp, const float* __restrict__ bp,
            float* __restrict__ out) {
    gemm_tile(Wp, bp, g_o, out);
}

// ---------------------------------------------------------------------------
// Fused flash attention with analytic relative-position bias.
// CTA = (head h, 64 query rows). Online softmax over 36 key tiles of 64.
// ---------------------------------------------------------------------------
#define SM_QSD 0                          // float2[32*64]  = 16384 B
#define SM_KS  16384                      // float [32*64]  =  8192 B
#define SM_VST (16384 + 8192)             // float [64*34]  =  8704 B
#define SM_PSD (16384 + 8192 + 8704)      // float2[64*66]  = 33792 B
#define SM_EMB (SM_PSD + 33792)           // float [296]    =  1184 B
#define SM_TOTAL (SM_EMB + 1184)          // 68256 B

__global__ void __launch_bounds__(256, 2)
attn_kernel(const float* __restrict__ emb) {
    extern __shared__ char smraw[];
    float2* qsd  = (float2*)(smraw + SM_QSD);
    float*  ks   = (float*) (smraw + SM_KS);
    float*  vsT  = (float*) (smraw + SM_VST);
    float2* psd  = (float2*)(smraw + SM_PSD);
    float*  embs = (float*) (smraw + SM_EMB);

    const int h   = blockIdx.y;
    const int n0  = blockIdx.x * 64;
    const int tid = threadIdx.x;
    const int ti  = tid >> 4, tj = tid & 15;
    const int i0  = ti * 4,   j0 = tj * 4;
    const int d0  = tj * 2;

    // emb table into smem; pad row (36) forced to zero
    for (int idx = tid; idx < 296; idx += 256)
        embs[idx] = (idx >= 288) ? 0.f : emb[idx];

    const float* Qh = g_q + (h * HD) * NDIM;
    const float* Kh = g_k + (h * HD) * NDIM;
    const float* Vh = g_v + (h * HD) * NDIM;

    // Q tile (32 x 64) as duplicated f32x2 pairs, resident all kernel
#pragma unroll
    for (int e = 0; e < 8; e++) {
        int idx = tid + e * 256;
        int d = idx >> 6, i = idx & 63;
        float qv = Qh[d * NDIM + n0 + i];
        qsd[d * 64 + i] = make_float2(qv, qv);
    }

    int xn[4], yn[4];
#pragma unroll
    for (int ii = 0; ii < 4; ii++) {
        int n = n0 + i0 + ii;
        xn[ii] = n / 48; yn[ii] = n - 48 * xn[ii];
    }

    U64 o2[4];
#pragma unroll
    for (int ii = 0; ii < 4; ii++) o2[ii].u = 0ull;
    float mi[4] = {-1e30f, -1e30f, -1e30f, -1e30f};
    float li[4] = {0.f, 0.f, 0.f, 0.f};
    const float scale = 0.17677669529663687f;  // 32^-0.5

    for (int m0 = 0; m0 < NDIM; m0 += 64) {
        __syncthreads();
#pragma unroll
        for (int e = 0; e < 8; e++) {
            int idx = tid + e * 256;
            int d = idx >> 6, j = idx & 63;
            ks [d * 64 + j]  = Kh[d * NDIM + m0 + j];
            vsT[j * 34 + d]  = Vh[d * NDIM + m0 + j];
        }
        __syncthreads();

        // S = Q^T K  (4x4 per thread, packed over j pairs)
        U64 s2[4][2];
#pragma unroll
        for (int a = 0; a < 4; a++) { s2[a][0].u = 0ull; s2[a][1].u = 0ull; }
#pragma unroll
        for (int d = 0; d < 32; d++) {
            ulonglong2 qa = *(const ulonglong2*)(qsd + d * 64 + i0);
            ulonglong2 qb = *(const ulonglong2*)(qsd + d * 64 + i0 + 2);
            ulonglong2 kp = *(const ulonglong2*)(ks  + d * 64 + j0);
            ffma2(s2[0][0].u, qa.x, kp.x); ffma2(s2[0][1].u, qa.x, kp.y);
            ffma2(s2[1][0].u, qa.y, kp.x); ffma2(s2[1][1].u, qa.y, kp.y);
            ffma2(s2[2][0].u, qb.x, kp.x); ffma2(s2[2][1].u, qb.x, kp.y);
            ffma2(s2[3][0].u, qb.y, kp.x); ffma2(s2[3][1].u, qb.y, kp.y);
        }

        float s[4][4];
#pragma unroll
        for (int ii = 0; ii < 4; ii++) {
            s[ii][0] = s2[ii][0].f.x; s[ii][1] = s2[ii][0].f.y;
            s[ii][2] = s2[ii][1].f.x; s[ii][3] = s2[ii][1].f.y;
        }

        // scale + analytic relative-position bias
        int xm[4], ym[4];
#pragma unroll
        for (int jj = 0; jj < 4; jj++) {
            int m = m0 + j0 + jj;
            xm[jj] = m / 48; ym[jj] = m - 48 * xm[jj];
        }
#pragma unroll
        for (int ii = 0; ii < 4; ii++)
#pragma unroll
            for (int jj = 0; jj < 4; jj++) {
                int dx = xn[ii] - xm[jj]; dx = dx < 0 ? -dx : dx;
                int dy = yn[ii] - ym[jj]; dy = dy < 0 ? -dy : dy;
                float bb = (dx < 6 && dy < 6) ? embs[(dx * 6 + dy) * 8 + h] : 0.f;
                s[ii][jj] = s[ii][jj] * scale + bb;
            }

        // online softmax (row reductions across the 16 tj lanes)
        float mx[4];
#pragma unroll
        for (int ii = 0; ii < 4; ii++)
            mx[ii] = fmaxf(fmaxf(s[ii][0], s[ii][1]), fmaxf(s[ii][2], s[ii][3]));
#pragma unroll
        for (int off = 1; off < 16; off <<= 1)
#pragma unroll
            for (int ii = 0; ii < 4; ii++)
                mx[ii] = fmaxf(mx[ii], __shfl_xor_sync(0xffffffffu, mx[ii], off));

        float rf[4], rs[4];
#pragma unroll
        for (int ii = 0; ii < 4; ii++) {
            float mn = fmaxf(mi[ii], mx[ii]);
            rf[ii] = __expf(mi[ii] - mn);
            mi[ii] = mn;
            float p0 = __expf(s[ii][0] - mn);
            float p1 = __expf(s[ii][1] - mn);
            float p2 = __expf(s[ii][2] - mn);
            float p3 = __expf(s[ii][3] - mn);
            s[ii][0] = p0; s[ii][1] = p1; s[ii][2] = p2; s[ii][3] = p3;
            rs[ii] = (p0 + p1) + (p2 + p3);
        }
#pragma unroll
        for (int off = 1; off < 16; off <<= 1)
#pragma unroll
            for (int ii = 0; ii < 4; ii++)
                rs[ii] += __shfl_xor_sync(0xffffffffu, rs[ii], off);
#pragma unroll
        for (int ii = 0; ii < 4; ii++)
            li[ii] = li[ii] * rf[ii] + rs[ii];

        // stage P (duplicated pairs, transposed [j][i]) and rescale O
#pragma unroll
        for (int jj = 0; jj < 4; jj++)
#pragma unroll
            for (int ii = 0; ii < 4; ii++)
                psd[(j0 + jj) * 66 + i0 + ii] = make_float2(s[ii][jj], s[ii][jj]);
#pragma unroll
        for (int ii = 0; ii < 4; ii++) {
            o2[ii].f.x *= rf[ii];
            o2[ii].f.y *= rf[ii];
        }
        __syncthreads();

        // O[i][d0,d0+1] += sum_j P[i][j] * V[d][j]
#pragma unroll 8
        for (int j = 0; j < 64; j++) {
            ulonglong2 pa = *(const ulonglong2*)(psd + j * 66 + i0);
            ulonglong2 pb = *(const ulonglong2*)(psd + j * 66 + i0 + 2);
            unsigned long long vp = *(const unsigned long long*)(vsT + j * 34 + d0);
            ffma2(o2[0].u, pa.x, vp);
            ffma2(o2[1].u, pa.y, vp);
            ffma2(o2[2].u, pb.x, vp);
            ffma2(o2[3].u, pb.y, vp);
        }
    }

    float* Oh = g_o + (h * HD) * NDIM;
#pragma unroll
    for (int ii = 0; ii < 4; ii++) {
        float invl = 1.0f / li[ii];
        int n = n0 + i0 + ii;
        Oh[(d0 + 0) * NDIM + n] = o2[ii].f.x * invl;
        Oh[(d0 + 1) * NDIM + n] = o2[ii].f.y * invl;
    }
}

// ---------------------------------------------------------------------------
extern "C" void kernel_launch(void* const* d_in, const int* in_sizes, int n_in,
                              void* d_out, int out_size) {
    const float* x   = (const float*)d_in[0];
    const float* Wq  = (const float*)d_in[1];
    const float* bq  = (const float*)d_in[2];
    const float* Wk  = (const float*)d_in[3];
    const float* bk  = (const float*)d_in[4];
    const float* Wv  = (const float*)d_in[5];
    const float* bv  = (const float*)d_in[6];
    const float* Wp  = (const float*)d_in[7];
    const float* bp  = (const float*)d_in[8];
    const float* emb = (const float*)d_in[9];
    // d_in[10] = tokens (int32) — recomputed analytically in-kernel, unused
    float* out = (float*)d_out;

    cudaFuncSetAttribute(attn_kernel,
                         cudaFuncAttributeMaxDynamicSharedMemorySize, SM_TOTAL);

    qkv_kernel<<<dim3(36, 4, 3), 256>>>(x, Wq, bq, Wk, bk, Wv, bv);
    attn_kernel<<<dim3(36, HEADS), 256, SM_TOTAL>>>(emb);
    proj_kernel<<<dim3(36, 4), 256>>>(Wp, bp, out);
}